// round 2
// baseline (speedup 1.0000x reference)
#include <cuda_runtime.h>
#include <math.h>

#define BN 4
#define CN 64
#define HN 128
#define WN 128
#define HWN 16384

// ---------------- scratch (no allocations allowed) ----------------
__device__ float g_toff[BN * CN * HWN];   // conv1x1 (offset branch)   16MB
__device__ float g_tmask[BN * CN * HWN];  // conv1x1 (mask branch)     16MB
__device__ float g_off[BN * 18 * HWN];    // conv3x3 offsets (k*2+d)   4.7MB
__device__ float g_mask[BN * 9 * HWN];    // sigmoid(conv3x3)          2.4MB
__device__ float g_stats[BN * 32 * 2];    // per (b,group): mean, rstd

// ---------------- kernel 1: fused 1x1 convs (128 out channels) ----------------
__global__ __launch_bounds__(256) void k_conv1x1(const float* __restrict__ x,
                                                 const float* __restrict__ w1,
                                                 const float* __restrict__ w2)
{
    __shared__ float ws[64][128];  // [ci][co]  32KB
    __shared__ float sx[64][64];   // [ci][px]  16KB
    int tid = threadIdx.x;
    int b = blockIdx.y;
    int p0 = blockIdx.x * 64;

    for (int i = tid; i < 64 * 128; i += 256) {
        int ci = i >> 7, co = i & 127;
        ws[ci][co] = (co < 64) ? w1[co * 64 + ci] : w2[(co - 64) * 64 + ci];
    }
    const float* xb = x + (size_t)b * CN * HWN + p0;
    for (int i = tid; i < 64 * 64; i += 256) {
        int ci = i >> 6, px = i & 63;
        sx[ci][px] = xb[(size_t)ci * HWN + px];
    }
    __syncthreads();

    int pp = tid & 31;   // pixel pair 0..31
    int cs = tid >> 5;   // out-channel slot 0..7 (16 channels each)
    float a0[16], a1[16];
#pragma unroll
    for (int j = 0; j < 16; j++) { a0[j] = 0.f; a1[j] = 0.f; }

#pragma unroll 4
    for (int ci = 0; ci < 64; ci++) {
        float2 xv = *(const float2*)&sx[ci][2 * pp];
        const float4* wr = (const float4*)&ws[ci][cs * 16];
#pragma unroll
        for (int q = 0; q < 4; q++) {
            float4 w4 = wr[q];
            a0[q * 4 + 0] += xv.x * w4.x;  a1[q * 4 + 0] += xv.y * w4.x;
            a0[q * 4 + 1] += xv.x * w4.y;  a1[q * 4 + 1] += xv.y * w4.y;
            a0[q * 4 + 2] += xv.x * w4.z;  a1[q * 4 + 2] += xv.y * w4.z;
            a0[q * 4 + 3] += xv.x * w4.w;  a1[q * 4 + 3] += xv.y * w4.w;
        }
    }

#pragma unroll
    for (int j = 0; j < 16; j++) {
        int co = cs * 16 + j;
        float* dst = (co < 64) ? g_toff : g_tmask;
        int c = co & 63;
        float2 v = make_float2(a0[j], a1[j]);
        *(float2*)&dst[((size_t)(b * 64 + c)) * HWN + p0 + 2 * pp] = v;
    }
}

// ---------------- kernel 2: 3x3 conv, pad 1 ----------------
// MODE 0: g_toff -> g_off (18 out channels), MODE 1: g_tmask -> sigmoid -> g_mask (9 out)
template <int MODE, int NCO, int NCOP>
__global__ __launch_bounds__(256) void k_conv3x3(const float* __restrict__ w)
{
    const float* in = (MODE == 0) ? g_toff : g_tmask;
    float* out = (MODE == 0) ? g_off : g_mask;

    __shared__ float tile[8][18][19];
    __shared__ float ws[8][9][NCOP];

    int tid = threadIdx.x;
    int b = blockIdx.z;
    int ty0 = blockIdx.y * 16, tx0 = blockIdx.x * 16;
    int ty = tid >> 4, tx = tid & 15;

    float4 acc[NCOP / 4];
#pragma unroll
    for (int q = 0; q < NCOP / 4; q++) acc[q] = make_float4(0.f, 0.f, 0.f, 0.f);

    for (int ch = 0; ch < 8; ch++) {
        int ci0 = ch * 8;
        __syncthreads();
        for (int i = tid; i < 8 * 18 * 18; i += 256) {
            int ci = i / 324, r = i % 324, iy = r / 18, ix = r % 18;
            int gy = ty0 - 1 + iy, gx = tx0 - 1 + ix;
            float v = 0.f;
            if ((unsigned)gy < 128u && (unsigned)gx < 128u)
                v = in[((size_t)(b * 64 + ci0 + ci)) * HWN + gy * WN + gx];
            tile[ci][iy][ix] = v;
        }
        for (int i = tid; i < 8 * 9 * NCOP; i += 256) {
            int ci = i / (9 * NCOP), r = i % (9 * NCOP), tap = r / NCOP, co = r % NCOP;
            ws[ci][tap][co] = (co < NCO) ? w[((size_t)co * 64 + ci0 + ci) * 9 + tap] : 0.f;
        }
        __syncthreads();

#pragma unroll 2
        for (int ci = 0; ci < 8; ci++) {
#pragma unroll
            for (int ky = 0; ky < 3; ky++) {
                const float* row = tile[ci][ty + ky];
#pragma unroll
                for (int kx = 0; kx < 3; kx++) {
                    float xv = row[tx + kx];
                    const float4* wp = (const float4*)ws[ci][ky * 3 + kx];
#pragma unroll
                    for (int q = 0; q < NCOP / 4; q++) {
                        float4 w4 = wp[q];
                        acc[q].x += xv * w4.x;
                        acc[q].y += xv * w4.y;
                        acc[q].z += xv * w4.z;
                        acc[q].w += xv * w4.w;
                    }
                }
            }
        }
    }

    int hw = (ty0 + ty) * WN + tx0 + tx;
    const float* accf = (const float*)acc;
#pragma unroll
    for (int co = 0; co < NCO; co++) {
        float v = accf[co];
        if (MODE == 1) v = 1.f / (1.f + expf(-v));
        out[((size_t)(b * NCO + co)) * HWN + hw] = v;
    }
}

// ---------------- kernel 3: deformable sampling + combine + bias ----------------
// dynamic smem: tile 16*28*29 + 5 tap arrays of 9*256 + 576 weights = 25088 floats
#define K3_SMEM_FLOATS (16 * 28 * 29 + 5 * 2304 + 576)

__global__ __launch_bounds__(256) void k_deform(const float* __restrict__ x,
                                                const float* __restrict__ wq,
                                                const float* __restrict__ bias,
                                                float* __restrict__ out)
{
    extern __shared__ float sm[];
    float* tile = sm;                    // [16][28][29]
    float* s_wy = tile + 16 * 28 * 29;   // [9][256]
    float* s_wx = s_wy + 2304;
    float* s_m  = s_wx + 2304;
    int*   s_y0 = (int*)(s_m + 2304);
    int*   s_x0 = s_y0 + 2304;
    float* s_w  = (float*)(s_x0 + 2304); // [64][9]

    int tid = threadIdx.x;
    int b = blockIdx.z;
    int ty0 = blockIdx.y * 16, tx0 = blockIdx.x * 16;
    int ty = tid >> 4, tx = tid & 15;
    int gh = ty0 + ty, gw = tx0 + tx;
    int hw = gh * WN + gw;

    for (int i = tid; i < 576; i += 256) s_w[i] = wq[i];

#pragma unroll
    for (int k = 0; k < 9; k++) {
        int ky = k / 3 - 1, kx = k % 3 - 1;
        float oy = g_off[((size_t)(b * 18 + 2 * k)) * HWN + hw];
        float ox = g_off[((size_t)(b * 18 + 2 * k + 1)) * HWN + hw];
        float m  = g_mask[((size_t)(b * 9 + k)) * HWN + hw];
        float py = (float)(gh + ky) + oy;
        float px = (float)(gw + kx) + ox;
        float y0f = floorf(py), x0f = floorf(px);
        s_wy[k * 256 + tid] = py - y0f;
        s_wx[k * 256 + tid] = px - x0f;
        s_m [k * 256 + tid] = m;
        s_y0[k * 256 + tid] = (int)y0f;
        s_x0[k * 256 + tid] = (int)x0f;
    }

    for (int ch = 0; ch < 4; ch++) {
        int ci0 = ch * 16;
        __syncthreads();
        for (int i = tid; i < 16 * 784; i += 256) {
            int ci = i / 784, r = i % 784, iy = r / 28, ix = r % 28;
            int gy = ty0 - 6 + iy, gx = tx0 - 6 + ix;
            float v = 0.f;
            if ((unsigned)gy < 128u && (unsigned)gx < 128u)
                v = x[((size_t)(b * 64 + ci0 + ci)) * HWN + gy * WN + gx];
            tile[ci * (28 * 29) + iy * 29 + ix] = v;
        }
        __syncthreads();

        float acc[16];
#pragma unroll
        for (int j = 0; j < 16; j++) acc[j] = 0.f;

#pragma unroll 1
        for (int k = 0; k < 9; k++) {
            float wy = s_wy[k * 256 + tid], wx = s_wx[k * 256 + tid];
            float m  = s_m [k * 256 + tid];
            int y0 = s_y0[k * 256 + tid], x0 = s_x0[k * 256 + tid];
            float a00 = m * (1.f - wy) * (1.f - wx);
            float a01 = m * (1.f - wy) * wx;
            float a10 = m * wy * (1.f - wx);
            float a11 = m * wy * wx;
            int ly = y0 - (ty0 - 6), lx = x0 - (tx0 - 6);
            if ((unsigned)ly < 27u && (unsigned)lx < 27u) {
                const float* tp = &tile[ly * 29 + lx];
#pragma unroll
                for (int ci = 0; ci < 16; ci++) {
                    const float* t = tp + ci * (28 * 29);
                    float v = a00 * t[0] + a01 * t[1] + a10 * t[29] + a11 * t[30];
                    acc[ci] += s_w[(ci0 + ci) * 9 + k] * v;
                }
            } else {
                int y1 = y0 + 1, x1 = x0 + 1;
                bool b00 = (unsigned)y0 < 128u && (unsigned)x0 < 128u;
                bool b01 = (unsigned)y0 < 128u && (unsigned)x1 < 128u;
                bool b10 = (unsigned)y1 < 128u && (unsigned)x0 < 128u;
                bool b11 = (unsigned)y1 < 128u && (unsigned)x1 < 128u;
                const float* xb = x + ((size_t)(b * 64 + ci0)) * HWN;
#pragma unroll
                for (int ci = 0; ci < 16; ci++) {
                    const float* p = xb + (size_t)ci * HWN;
                    float f00 = b00 ? __ldg(p + y0 * WN + x0) : 0.f;
                    float f01 = b01 ? __ldg(p + y0 * WN + x1) : 0.f;
                    float f10 = b10 ? __ldg(p + y1 * WN + x0) : 0.f;
                    float f11 = b11 ? __ldg(p + y1 * WN + x1) : 0.f;
                    float v = a00 * f00 + a01 * f01 + a10 * f10 + a11 * f11;
                    acc[ci] += s_w[(ci0 + ci) * 9 + k] * v;
                }
            }
        }
#pragma unroll
        for (int ci = 0; ci < 16; ci++) {
            int c = ci0 + ci;
            out[((size_t)(b * 64 + c)) * HWN + hw] = acc[ci] + bias[c];
        }
    }
}

// ---------------- kernel 4: per-(b,group) mean/var (deterministic) ----------------
__global__ __launch_bounds__(256) void k_stats(const float* __restrict__ o)
{
    int bg = blockIdx.x;          // b*32 + g
    int b = bg >> 5, g = bg & 31;
    const float* p = o + ((size_t)(b * 64 + g * 2)) * HWN;  // 2 contiguous channels
    int tid = threadIdx.x;
    float s = 0.f, sq = 0.f;
    for (int i = tid; i < 2 * HWN; i += 256) {
        float v = p[i];
        s += v; sq += v * v;
    }
    __shared__ float ss[256], sqs[256];
    ss[tid] = s; sqs[tid] = sq;
    __syncthreads();
    for (int st = 128; st > 0; st >>= 1) {
        if (tid < st) { ss[tid] += ss[tid + st]; sqs[tid] += sqs[tid + st]; }
        __syncthreads();
    }
    if (tid == 0) {
        float mean = ss[0] * (1.f / 32768.f);
        float var  = sqs[0] * (1.f / 32768.f) - mean * mean;
        g_stats[bg * 2 + 0] = mean;
        g_stats[bg * 2 + 1] = rsqrtf(var + 1e-5f);
    }
}

// ---------------- kernel 5: normalize + affine + exact GELU (in place) ----------------
__global__ __launch_bounds__(256) void k_gn_gelu(float* __restrict__ o,
                                                 const float* __restrict__ gamma,
                                                 const float* __restrict__ beta)
{
    size_t i4 = (size_t)blockIdx.x * 256 + threadIdx.x;
    size_t i = i4 * 4;
    int c = (int)((i >> 14) & 63);
    int b = (int)(i >> 20);
    int g = c >> 1;
    float mean = g_stats[(b * 32 + g) * 2 + 0];
    float rstd = g_stats[(b * 32 + g) * 2 + 1];
    float sc = rstd * gamma[c];
    float sh = beta[c] - mean * sc;
    float4 v = ((float4*)o)[i4];
    float t;
    t = v.x * sc + sh; v.x = 0.5f * t * (1.f + erff(t * 0.70710678118654752f));
    t = v.y * sc + sh; v.y = 0.5f * t * (1.f + erff(t * 0.70710678118654752f));
    t = v.z * sc + sh; v.z = 0.5f * t * (1.f + erff(t * 0.70710678118654752f));
    t = v.w * sc + sh; v.w = 0.5f * t * (1.f + erff(t * 0.70710678118654752f));
    ((float4*)o)[i4] = v;
}

// ---------------- launch ----------------
extern "C" void kernel_launch(void* const* d_in, const int* in_sizes, int n_in,
                              void* d_out, int out_size)
{
    const float* x       = (const float*)d_in[0];
    const float* w_off1  = (const float*)d_in[1];
    const float* w_off2  = (const float*)d_in[2];
    const float* w_mask1 = (const float*)d_in[3];
    const float* w_mask2 = (const float*)d_in[4];
    const float* weight  = (const float*)d_in[5];
    const float* bias    = (const float*)d_in[6];
    const float* gamma   = (const float*)d_in[7];
    const float* beta    = (const float*)d_in[8];
    float* out = (float*)d_out;

    cudaFuncSetAttribute(k_deform, cudaFuncAttributeMaxDynamicSharedMemorySize,
                         K3_SMEM_FLOATS * 4);

    k_conv1x1<<<dim3(HWN / 64, BN), 256>>>(x, w_off1, w_mask1);
    k_conv3x3<0, 18, 20><<<dim3(WN / 16, HN / 16, BN), 256>>>(w_off2);
    k_conv3x3<1, 9, 12><<<dim3(WN / 16, HN / 16, BN), 256>>>(w_mask2);
    k_deform<<<dim3(WN / 16, HN / 16, BN), 256, K3_SMEM_FLOATS * 4>>>(x, weight, bias, out);
    k_stats<<<BN * 32, 256>>>(out);
    k_gn_gelu<<<(BN * CN * HWN) / (4 * 256), 256>>>(out, gamma, beta);
}

// round 3
// speedup vs baseline: 1.4185x; 1.4185x over previous
#include <cuda_runtime.h>
#include <math.h>

#define BN 4
#define CN 64
#define HN 128
#define WN 128
#define HWN 16384

// ---------------- scratch ----------------
__device__ float g_off[BN * 18 * HWN];    // composed conv3x3 offsets (2k, 2k+1)
__device__ float g_mask[BN * 9 * HWN];    // sigmoid(composed conv3x3)
__device__ float g_wc[64 * 9 * 28];       // composed weights [ci][tap][co28]
__device__ float g_stats[BN * 32 * 2];

typedef unsigned long long u64;

__device__ __forceinline__ u64 fma2(u64 a, u64 b, u64 c) {
    u64 d; asm("fma.rn.f32x2 %0, %1, %2, %3;" : "=l"(d) : "l"(a), "l"(b), "l"(c)); return d;
}
__device__ __forceinline__ u64 pack2(float x, float y) {
    u64 d; asm("mov.b64 %0, {%1, %2};" : "=l"(d) : "f"(x), "f"(y)); return d;
}
__device__ __forceinline__ float2 unpack2(u64 v) {
    float2 r; asm("mov.b64 {%0, %1}, %2;" : "=f"(r.x), "=f"(r.y) : "l"(v)); return r;
}

// ---------------- kernel 0: compose 1x1 into 3x3 weights ----------------
// Wc[ci][tap][co] = sum_c w2[co][c][tap] * w1[c][ci];  co 0..17 = offset branch,
// co 18..26 = mask branch, co 27 = zero pad.
__global__ __launch_bounds__(256) void k_compose(const float* __restrict__ w_off1,
                                                 const float* __restrict__ w_off2,
                                                 const float* __restrict__ w_mask1,
                                                 const float* __restrict__ w_mask2)
{
    int ci = blockIdx.x;
    __shared__ float s1o[64], s1m[64];
    int t = threadIdx.x;
    if (t < 64) s1o[t] = w_off1[t * 64 + ci];
    else if (t < 128) s1m[t - 64] = w_mask1[(t - 64) * 64 + ci];
    __syncthreads();
    if (t < 252) {
        int tap = t / 28, co = t % 28;
        float s = 0.f;
        if (co < 18) {
            for (int c = 0; c < 64; c++) s += w_off2[(co * 64 + c) * 9 + tap] * s1o[c];
        } else if (co < 27) {
            int cm = co - 18;
            for (int c = 0; c < 64; c++) s += w_mask2[(cm * 64 + c) * 9 + tap] * s1m[c];
        }
        g_wc[ci * 252 + tap * 28 + co] = s;
    }
}

// ---------------- kernel 1: fused 3x3 conv (27 outputs) from x, f32x2 FMA ----------------
__global__ __launch_bounds__(256) void k_conv3x3full(const float* __restrict__ x)
{
    __shared__ float tile[16][10][35];   // [ci][row][col], 8x32 px + halo 1
    __shared__ float sw[4032];           // [ci 16][tap 9][co 28]
    int tid = threadIdx.x;
    int b = blockIdx.z;
    int tx0 = blockIdx.x * 32, ty0 = blockIdx.y * 8;
    int tx = tid & 31, ty = tid >> 5;

    u64 acc[14];
#pragma unroll
    for (int j = 0; j < 14; j++) acc[j] = 0ULL;

    for (int ch = 0; ch < 4; ch++) {
        int ci0 = ch * 16;
        __syncthreads();
        for (int i = tid; i < 16 * 10 * 34; i += 256) {
            int ci = i / 340, r = i % 340, iy = r / 34, ix = r % 34;
            int gy = ty0 - 1 + iy, gx = tx0 - 1 + ix;
            float v = 0.f;
            if ((unsigned)gy < 128u && (unsigned)gx < 128u)
                v = x[((size_t)(b * 64 + ci0 + ci)) * HWN + gy * WN + gx];
            tile[ci][iy][ix] = v;
        }
        for (int i = tid; i < 4032; i += 256)
            sw[i] = g_wc[ci0 * 252 + i];
        __syncthreads();

#pragma unroll 1
        for (int ci = 0; ci < 16; ci++) {
#pragma unroll
            for (int ky = 0; ky < 3; ky++) {
                const float* row = &tile[ci][ty + ky][tx];
#pragma unroll
                for (int kx = 0; kx < 3; kx++) {
                    float xv = row[kx];
                    u64 x2 = pack2(xv, xv);
                    const u64* wp = (const u64*)&sw[ci * 252 + (ky * 3 + kx) * 28];
#pragma unroll
                    for (int j = 0; j < 14; j++) acc[j] = fma2(x2, wp[j], acc[j]);
                }
            }
        }
    }

    int hw = (ty0 + ty) * WN + tx0 + tx;
    float o[28];
#pragma unroll
    for (int j = 0; j < 14; j++) { float2 v = unpack2(acc[j]); o[2 * j] = v.x; o[2 * j + 1] = v.y; }
#pragma unroll
    for (int co = 0; co < 18; co++)
        g_off[((size_t)(b * 18 + co)) * HWN + hw] = o[co];
#pragma unroll
    for (int k = 0; k < 9; k++)
        g_mask[((size_t)(b * 9 + k)) * HWN + hw] = 1.f / (1.f + __expf(-o[18 + k]));
}

// ---------------- kernel 2: deformable sampling + combine + bias ----------------
// block = 128 threads = 4 rows x 32 cols; halo 4; taps live in registers.
__global__ __launch_bounds__(128, 5) void k_deform(const float* __restrict__ x,
                                                   const float* __restrict__ wq,
                                                   const float* __restrict__ bias,
                                                   float* __restrict__ out)
{
    __shared__ float tile[16 * 12 * 41];  // [ci][12 rows][41 cols]
    __shared__ float s_w[576];
    int tid = threadIdx.x;
    int b = blockIdx.z;
    int tx0 = blockIdx.x * 32, ty0 = blockIdx.y * 4;
    int tx = tid & 31, ty = tid >> 5;
    int gh = ty0 + ty, gw = tx0 + tx;
    int hw = gh * WN + gw;

    for (int i = tid; i < 576; i += 128) s_w[i] = wq[i];

    float a00[9], a01[9], a10[9], a11[9];
    int lyA[9], lxA[9];
    const float* offb = g_off + (size_t)b * 18 * HWN + hw;
    const float* mb   = g_mask + (size_t)b * 9 * HWN + hw;
#pragma unroll
    for (int k = 0; k < 9; k++) {
        int ky = k / 3 - 1, kx = k % 3 - 1;
        float oy = offb[(size_t)(2 * k) * HWN];
        float ox = offb[(size_t)(2 * k + 1) * HWN];
        float m  = mb[(size_t)k * HWN];
        float py = (float)(gh + ky) + oy;
        float px = (float)(gw + kx) + ox;
        float yf = floorf(py), xf = floorf(px);
        float wy = py - yf, wx = px - xf;
        float b1 = m * wy, b0 = m - b1;
        a00[k] = b0 - b0 * wx; a01[k] = b0 * wx;
        a10[k] = b1 - b1 * wx; a11[k] = b1 * wx;
        lyA[k] = (int)yf - (ty0 - 4);
        lxA[k] = (int)xf - (tx0 - 4);
    }

    for (int ch = 0; ch < 4; ch++) {
        int ci0 = ch * 16;
        __syncthreads();
        for (int i = tid; i < 16 * 12 * 41; i += 128) {
            int r = i % 492, iy = r / 41, ix = r % 41;
            int ci = i / 492;
            int gy = ty0 - 4 + iy, gx = tx0 - 4 + ix;
            float v = 0.f;
            if ((unsigned)gy < 128u && (unsigned)gx < 128u)
                v = x[((size_t)(b * 64 + ci)) * HWN + (size_t)ci0 * HWN + gy * WN + gx];
            tile[i] = v;
        }
        __syncthreads();

        float acc[16];
#pragma unroll
        for (int j = 0; j < 16; j++) acc[j] = 0.f;

#pragma unroll
        for (int k = 0; k < 9; k++) {
            float c00 = a00[k], c01 = a01[k], c10 = a10[k], c11 = a11[k];
            int ly = lyA[k], lx = lxA[k];
            if ((unsigned)ly < 11u && (unsigned)lx < 40u) {
                const float* tp = &tile[ly * 41 + lx];
#pragma unroll
                for (int ci = 0; ci < 16; ci++) {
                    const float* t = tp + ci * 492;
                    float v = c00 * t[0] + c01 * t[1] + c10 * t[41] + c11 * t[42];
                    acc[ci] += s_w[(ci0 + ci) * 9 + k] * v;
                }
            } else {
                int y0 = ly + ty0 - 4, x0 = lx + tx0 - 4;
                int y1 = y0 + 1, x1 = x0 + 1;
                bool v00 = (unsigned)y0 < 128u && (unsigned)x0 < 128u;
                bool v01 = (unsigned)y0 < 128u && (unsigned)x1 < 128u;
                bool v10 = (unsigned)y1 < 128u && (unsigned)x0 < 128u;
                bool v11 = (unsigned)y1 < 128u && (unsigned)x1 < 128u;
                const float* xb = x + ((size_t)(b * 64 + ci0)) * HWN;
#pragma unroll
                for (int ci = 0; ci < 16; ci++) {
                    const float* p = xb + (size_t)ci * HWN;
                    float f00 = v00 ? __ldg(p + y0 * WN + x0) : 0.f;
                    float f01 = v01 ? __ldg(p + y0 * WN + x1) : 0.f;
                    float f10 = v10 ? __ldg(p + y1 * WN + x0) : 0.f;
                    float f11 = v11 ? __ldg(p + y1 * WN + x1) : 0.f;
                    float v = c00 * f00 + c01 * f01 + c10 * f10 + c11 * f11;
                    acc[ci] += s_w[(ci0 + ci) * 9 + k] * v;
                }
            }
        }
#pragma unroll
        for (int ci = 0; ci < 16; ci++) {
            int c = ci0 + ci;
            out[((size_t)(b * 64 + c)) * HWN + hw] = acc[ci] + bias[c];
        }
    }
}

// ---------------- kernel 3: per-(b,group) mean/var ----------------
__global__ __launch_bounds__(256) void k_stats(const float* __restrict__ o)
{
    int bg = blockIdx.x;
    int b = bg >> 5, g = bg & 31;
    const float* p = o + ((size_t)(b * 64 + g * 2)) * HWN;
    int tid = threadIdx.x;
    float s = 0.f, sq = 0.f;
    for (int i = tid; i < 2 * HWN; i += 256) {
        float v = p[i];
        s += v; sq += v * v;
    }
    __shared__ float ss[256], sqs[256];
    ss[tid] = s; sqs[tid] = sq;
    __syncthreads();
    for (int st = 128; st > 0; st >>= 1) {
        if (tid < st) { ss[tid] += ss[tid + st]; sqs[tid] += sqs[tid + st]; }
        __syncthreads();
    }
    if (tid == 0) {
        float mean = ss[0] * (1.f / 32768.f);
        float var  = sqs[0] * (1.f / 32768.f) - mean * mean;
        g_stats[bg * 2 + 0] = mean;
        g_stats[bg * 2 + 1] = rsqrtf(var + 1e-5f);
    }
}

// ---------------- kernel 4: normalize + affine + exact GELU ----------------
__global__ __launch_bounds__(256) void k_gn_gelu(float* __restrict__ o,
                                                 const float* __restrict__ gamma,
                                                 const float* __restrict__ beta)
{
    size_t i4 = (size_t)blockIdx.x * 256 + threadIdx.x;
    size_t i = i4 * 4;
    int c = (int)((i >> 14) & 63);
    int b = (int)(i >> 20);
    int g = c >> 1;
    float mean = g_stats[(b * 32 + g) * 2 + 0];
    float rstd = g_stats[(b * 32 + g) * 2 + 1];
    float sc = rstd * gamma[c];
    float sh = beta[c] - mean * sc;
    float4 v = ((float4*)o)[i4];
    float t;
    t = v.x * sc + sh; v.x = 0.5f * t * (1.f + erff(t * 0.70710678118654752f));
    t = v.y * sc + sh; v.y = 0.5f * t * (1.f + erff(t * 0.70710678118654752f));
    t = v.z * sc + sh; v.z = 0.5f * t * (1.f + erff(t * 0.70710678118654752f));
    t = v.w * sc + sh; v.w = 0.5f * t * (1.f + erff(t * 0.70710678118654752f));
    ((float4*)o)[i4] = v;
}

// ---------------- launch ----------------
extern "C" void kernel_launch(void* const* d_in, const int* in_sizes, int n_in,
                              void* d_out, int out_size)
{
    const float* x       = (const float*)d_in[0];
    const float* w_off1  = (const float*)d_in[1];
    const float* w_off2  = (const float*)d_in[2];
    const float* w_mask1 = (const float*)d_in[3];
    const float* w_mask2 = (const float*)d_in[4];
    const float* weight  = (const float*)d_in[5];
    const float* bias    = (const float*)d_in[6];
    const float* gamma   = (const float*)d_in[7];
    const float* beta    = (const float*)d_in[8];
    float* out = (float*)d_out;

    k_compose<<<64, 256>>>(w_off1, w_off2, w_mask1, w_mask2);
    k_conv3x3full<<<dim3(WN / 32, HN / 8, BN), 256>>>(x);
    k_deform<<<dim3(WN / 32, HN / 4, BN), 128>>>(x, weight, bias, out);
    k_stats<<<BN * 32, 256>>>(out);
    k_gn_gelu<<<(BN * CN * HWN) / (4 * 256), 256>>>(out, gamma, beta);
}

// round 4
// speedup vs baseline: 1.5612x; 1.1006x over previous
#include <cuda_runtime.h>
#include <math.h>

#define BN 4
#define CN 64
#define HN 128
#define WN 128
#define HWN 16384

// ---------------- scratch ----------------
__device__ float g_off[BN * 18 * HWN];
__device__ float g_mask[BN * 9 * HWN];
__device__ float g_wc[64 * 9 * 28];       // composed weights [ci][tap][co28]
__device__ float g_part[512 * 2];         // per (b,g,quarter): sum, sumsq

typedef unsigned long long u64;

__device__ __forceinline__ u64 fma2(u64 a, u64 b, u64 c) {
    u64 d; asm("fma.rn.f32x2 %0, %1, %2, %3;" : "=l"(d) : "l"(a), "l"(b), "l"(c)); return d;
}
__device__ __forceinline__ u64 pack2(float x, float y) {
    u64 d; asm("mov.b64 %0, {%1, %2};" : "=l"(d) : "f"(x), "f"(y)); return d;
}
__device__ __forceinline__ float2 unpack2(u64 v) {
    float2 r; asm("mov.b64 {%0, %1}, %2;" : "=f"(r.x), "=f"(r.y) : "l"(v)); return r;
}

// ---------------- kernel 0: compose 1x1 into 3x3 weights ----------------
__global__ __launch_bounds__(256) void k_compose(const float* __restrict__ w_off1,
                                                 const float* __restrict__ w_off2,
                                                 const float* __restrict__ w_mask1,
                                                 const float* __restrict__ w_mask2)
{
    int ci = blockIdx.x;
    __shared__ float s1o[64], s1m[64];
    int t = threadIdx.x;
    if (t < 64) s1o[t] = w_off1[t * 64 + ci];
    else if (t < 128) s1m[t - 64] = w_mask1[(t - 64) * 64 + ci];
    __syncthreads();
    if (t < 252) {
        int tap = t / 28, co = t % 28;
        float s = 0.f;
        if (co < 18) {
            for (int c = 0; c < 64; c++) s += w_off2[(co * 64 + c) * 9 + tap] * s1o[c];
        } else if (co < 27) {
            int cm = co - 18;
            for (int c = 0; c < 64; c++) s += w_mask2[(cm * 64 + c) * 9 + tap] * s1m[c];
        }
        g_wc[ci * 252 + tap * 28 + co] = s;
    }
}

// ---------------- kernel 1: fused 3x3 conv, 2 px/thread, f32x2 ----------------
// block 128 thr = 32 cols x 4 row-slots; px A = row ty, px B = row ty+4.
__global__ __launch_bounds__(128, 4) void k_conv3x3full(const float* __restrict__ x)
{
    __shared__ __align__(16) float tile[8][10][35];  // 8 ci, 8 rows + halo, 32 cols + halo
    __shared__ __align__(16) float sw[2016];         // [ci 8][tap 9][co 28]
    int tid = threadIdx.x;
    int b = blockIdx.z;
    int tx0 = blockIdx.x * 32, ty0 = blockIdx.y * 8;
    int tx = tid & 31, ty = tid >> 5;   // ty 0..3

    u64 accA[14], accB[14];
#pragma unroll
    for (int j = 0; j < 14; j++) { accA[j] = 0ULL; accB[j] = 0ULL; }

    for (int ch = 0; ch < 8; ch++) {
        int ci0 = ch * 8;
        __syncthreads();
        for (int i = tid; i < 8 * 10 * 34; i += 128) {
            int ci = i / 340, r = i % 340, iy = r / 34, ix = r % 34;
            int gy = ty0 - 1 + iy, gx = tx0 - 1 + ix;
            float v = 0.f;
            if ((unsigned)gy < 128u && (unsigned)gx < 128u)
                v = x[((size_t)(b * 64 + ci0 + ci)) * HWN + gy * WN + gx];
            tile[ci][iy][ix] = v;
        }
        for (int i = tid; i < 2016; i += 128)
            sw[i] = g_wc[ci0 * 252 + i];
        __syncthreads();

#pragma unroll 1
        for (int ci = 0; ci < 8; ci++) {
#pragma unroll
            for (int ky = 0; ky < 3; ky++) {
                const float* rowA = &tile[ci][ty + ky][tx];
                const float* rowB = &tile[ci][ty + 4 + ky][tx];
#pragma unroll
                for (int kx = 0; kx < 3; kx++) {
                    u64 xA = pack2(rowA[kx], rowA[kx]);
                    u64 xB = pack2(rowB[kx], rowB[kx]);
                    const u64* wp = (const u64*)&sw[ci * 252 + (ky * 3 + kx) * 28];
#pragma unroll
                    for (int j = 0; j < 14; j++) {
                        u64 w = wp[j];
                        accA[j] = fma2(xA, w, accA[j]);
                        accB[j] = fma2(xB, w, accB[j]);
                    }
                }
            }
        }
    }

#pragma unroll
    for (int px = 0; px < 2; px++) {
        int hw = (ty0 + ty + px * 4) * WN + tx0 + tx;
        const u64* acc = px ? accB : accA;
        float o[28];
#pragma unroll
        for (int j = 0; j < 14; j++) { float2 v = unpack2(acc[j]); o[2 * j] = v.x; o[2 * j + 1] = v.y; }
#pragma unroll
        for (int co = 0; co < 18; co++)
            g_off[((size_t)(b * 18 + co)) * HWN + hw] = o[co];
#pragma unroll
        for (int k = 0; k < 9; k++)
            g_mask[((size_t)(b * 9 + k)) * HWN + hw] = 1.f / (1.f + __expf(-o[18 + k]));
    }
}

// ---------------- kernel 2: deformable sampling + combine + bias ----------------
__global__ __launch_bounds__(128, 5) void k_deform(const float* __restrict__ x,
                                                   const float* __restrict__ wq,
                                                   const float* __restrict__ bias,
                                                   float* __restrict__ out)
{
    __shared__ float tile[16 * 12 * 41];
    __shared__ float s_w[576];
    int tid = threadIdx.x;
    int b = blockIdx.z;
    int tx0 = blockIdx.x * 32, ty0 = blockIdx.y * 4;
    int tx = tid & 31, ty = tid >> 5;
    int gh = ty0 + ty, gw = tx0 + tx;
    int hw = gh * WN + gw;

    for (int i = tid; i < 576; i += 128) s_w[i] = wq[i];

    float a00[9], a01[9], a10[9], a11[9];
    int lyA[9], lxA[9];
    const float* offb = g_off + (size_t)b * 18 * HWN + hw;
    const float* mb   = g_mask + (size_t)b * 9 * HWN + hw;
#pragma unroll
    for (int k = 0; k < 9; k++) {
        int ky = k / 3 - 1, kx = k % 3 - 1;
        float oy = offb[(size_t)(2 * k) * HWN];
        float ox = offb[(size_t)(2 * k + 1) * HWN];
        float m  = mb[(size_t)k * HWN];
        float py = (float)(gh + ky) + oy;
        float px = (float)(gw + kx) + ox;
        float yf = floorf(py), xf = floorf(px);
        float wy = py - yf, wx = px - xf;
        float b1 = m * wy, b0 = m - b1;
        a00[k] = b0 - b0 * wx; a01[k] = b0 * wx;
        a10[k] = b1 - b1 * wx; a11[k] = b1 * wx;
        lyA[k] = (int)yf - (ty0 - 4);
        lxA[k] = (int)xf - (tx0 - 4);
    }

    for (int ch = 0; ch < 4; ch++) {
        int ci0 = ch * 16;
        __syncthreads();
        for (int i = tid; i < 16 * 12 * 41; i += 128) {
            int r = i % 492, iy = r / 41, ix = r % 41;
            int ci = i / 492;
            int gy = ty0 - 4 + iy, gx = tx0 - 4 + ix;
            float v = 0.f;
            if ((unsigned)gy < 128u && (unsigned)gx < 128u)
                v = x[((size_t)(b * 64 + ci0 + ci)) * HWN + gy * WN + gx];
            tile[i] = v;
        }
        __syncthreads();

        float acc[16];
#pragma unroll
        for (int j = 0; j < 16; j++) acc[j] = 0.f;

#pragma unroll
        for (int k = 0; k < 9; k++) {
            float c00 = a00[k], c01 = a01[k], c10 = a10[k], c11 = a11[k];
            int ly = lyA[k], lx = lxA[k];
            if ((unsigned)ly < 11u && (unsigned)lx < 40u) {
                const float* tp = &tile[ly * 41 + lx];
#pragma unroll
                for (int ci = 0; ci < 16; ci++) {
                    const float* t = tp + ci * 492;
                    float v = c00 * t[0] + c01 * t[1] + c10 * t[41] + c11 * t[42];
                    acc[ci] += s_w[(ci0 + ci) * 9 + k] * v;
                }
            } else {
                int y0 = ly + ty0 - 4, x0 = lx + tx0 - 4;
                int y1 = y0 + 1, x1 = x0 + 1;
                bool v00 = (unsigned)y0 < 128u && (unsigned)x0 < 128u;
                bool v01 = (unsigned)y0 < 128u && (unsigned)x1 < 128u;
                bool v10 = (unsigned)y1 < 128u && (unsigned)x0 < 128u;
                bool v11 = (unsigned)y1 < 128u && (unsigned)x1 < 128u;
                const float* xb = x + ((size_t)(b * 64 + ci0)) * HWN;
#pragma unroll
                for (int ci = 0; ci < 16; ci++) {
                    const float* p = xb + (size_t)ci * HWN;
                    float f00 = v00 ? __ldg(p + y0 * WN + x0) : 0.f;
                    float f01 = v01 ? __ldg(p + y0 * WN + x1) : 0.f;
                    float f10 = v10 ? __ldg(p + y1 * WN + x0) : 0.f;
                    float f11 = v11 ? __ldg(p + y1 * WN + x1) : 0.f;
                    float v = c00 * f00 + c01 * f01 + c10 * f10 + c11 * f11;
                    acc[ci] += s_w[(ci0 + ci) * 9 + k] * v;
                }
            }
        }
#pragma unroll
        for (int ci = 0; ci < 16; ci++) {
            int c = ci0 + ci;
            out[((size_t)(b * 64 + c)) * HWN + hw] = acc[ci] + bias[c];
        }
    }
}

// ---------------- kernel 3: partial mean/var (4 quarters per group) ----------------
__global__ __launch_bounds__(256) void k_stats(const float* __restrict__ o)
{
    int id = blockIdx.x;          // bg*4 + q
    int q = id & 3, bg = id >> 2;
    int b = bg >> 5, g = bg & 31;
    const float4* p = (const float4*)(o + ((size_t)(b * 64 + g * 2)) * HWN) + q * 2048;
    int tid = threadIdx.x;
    float s = 0.f, sq = 0.f;
#pragma unroll
    for (int i = 0; i < 8; i++) {
        float4 v = p[tid + i * 256];
        s += v.x + v.y + v.z + v.w;
        sq += v.x * v.x + v.y * v.y + v.z * v.z + v.w * v.w;
    }
    __shared__ float ss[256], sqs[256];
    ss[tid] = s; sqs[tid] = sq;
    __syncthreads();
    for (int st = 128; st > 0; st >>= 1) {
        if (tid < st) { ss[tid] += ss[tid + st]; sqs[tid] += sqs[tid + st]; }
        __syncthreads();
    }
    if (tid == 0) {
        g_part[id * 2 + 0] = ss[0];
        g_part[id * 2 + 1] = sqs[0];
    }
}

// ---------------- kernel 4: finalize stats + normalize + affine + GELU ----------------
__global__ __launch_bounds__(256) void k_gn_gelu(float* __restrict__ o,
                                                 const float* __restrict__ gamma,
                                                 const float* __restrict__ beta)
{
    __shared__ float s_sc, s_sh;
    size_t i0 = (size_t)blockIdx.x * 1024;   // 1024 contiguous px, single (b,c)
    int c = (int)((i0 >> 14) & 63);
    int b = (int)(i0 >> 20);
    int g = c >> 1;
    if (threadIdx.x == 0) {
        int base = (b * 32 + g) * 4;
        float s = 0.f, sq = 0.f;
#pragma unroll
        for (int q = 0; q < 4; q++) {
            s  += g_part[(base + q) * 2 + 0];
            sq += g_part[(base + q) * 2 + 1];
        }
        float mean = s * (1.f / 32768.f);
        float var  = sq * (1.f / 32768.f) - mean * mean;
        float rstd = rsqrtf(var + 1e-5f);
        float sc = rstd * gamma[c];
        s_sc = sc;
        s_sh = beta[c] - mean * sc;
    }
    __syncthreads();
    float sc = s_sc, sh = s_sh;
    size_t i4 = i0 / 4 + threadIdx.x;
    float4 v = ((float4*)o)[i4];
    float t;
    t = v.x * sc + sh; v.x = 0.5f * t * (1.f + erff(t * 0.70710678118654752f));
    t = v.y * sc + sh; v.y = 0.5f * t * (1.f + erff(t * 0.70710678118654752f));
    t = v.z * sc + sh; v.z = 0.5f * t * (1.f + erff(t * 0.70710678118654752f));
    t = v.w * sc + sh; v.w = 0.5f * t * (1.f + erff(t * 0.70710678118654752f));
    ((float4*)o)[i4] = v;
}

// ---------------- launch ----------------
extern "C" void kernel_launch(void* const* d_in, const int* in_sizes, int n_in,
                              void* d_out, int out_size)
{
    const float* x       = (const float*)d_in[0];
    const float* w_off1  = (const float*)d_in[1];
    const float* w_off2  = (const float*)d_in[2];
    const float* w_mask1 = (const float*)d_in[3];
    const float* w_mask2 = (const float*)d_in[4];
    const float* weight  = (const float*)d_in[5];
    const float* bias    = (const float*)d_in[6];
    const float* gamma   = (const float*)d_in[7];
    const float* beta    = (const float*)d_in[8];
    float* out = (float*)d_out;

    k_compose<<<64, 256>>>(w_off1, w_off2, w_mask1, w_mask2);
    k_conv3x3full<<<dim3(WN / 32, HN / 8, BN), 128>>>(x);
    k_deform<<<dim3(WN / 32, HN / 4, BN), 128>>>(x, weight, bias, out);
    k_stats<<<512, 256>>>(out);
    k_gn_gelu<<<4096, 256>>>(out, gamma, beta);
}

// round 5
// speedup vs baseline: 1.6235x; 1.0399x over previous
#include <cuda_runtime.h>
#include <math.h>

#define BN 4
#define CN 64
#define HN 128
#define WN 128
#define HWN 16384
#define TCH 20   // channel-last tile stride (16 ci + 4 pad) -> conflict-free LDS.128

// ---------------- scratch ----------------
__device__ float g_offp[2 * BN * 18 * HWN];   // split-K partial conv outputs (offsets)
__device__ float g_maskp[2 * BN * 9 * HWN];   // split-K partial conv outputs (pre-sigmoid mask)
__device__ float g_wc[64 * 9 * 28];           // composed weights [ci][tap][co28]
__device__ float g_part[1024 * 2];            // per (b,g,segment): sum, sumsq

typedef unsigned long long u64;

__device__ __forceinline__ u64 fma2(u64 a, u64 b, u64 c) {
    u64 d; asm("fma.rn.f32x2 %0, %1, %2, %3;" : "=l"(d) : "l"(a), "l"(b), "l"(c)); return d;
}
__device__ __forceinline__ u64 mul2(u64 a, u64 b) {
    u64 d; asm("mul.rn.f32x2 %0, %1, %2;" : "=l"(d) : "l"(a), "l"(b)); return d;
}
__device__ __forceinline__ u64 pack2(float x, float y) {
    u64 d; asm("mov.b64 %0, {%1, %2};" : "=l"(d) : "f"(x), "f"(y)); return d;
}
__device__ __forceinline__ float2 unpack2(u64 v) {
    float2 r; asm("mov.b64 {%0, %1}, %2;" : "=f"(r.x), "=f"(r.y) : "l"(v)); return r;
}

// ---------------- kernel 0: compose 1x1 into 3x3 weights ----------------
__global__ __launch_bounds__(256) void k_compose(const float* __restrict__ w_off1,
                                                 const float* __restrict__ w_off2,
                                                 const float* __restrict__ w_mask1,
                                                 const float* __restrict__ w_mask2)
{
    int ci = blockIdx.x;
    __shared__ float s1o[64], s1m[64];
    int t = threadIdx.x;
    if (t < 64) s1o[t] = w_off1[t * 64 + ci];
    else if (t < 128) s1m[t - 64] = w_mask1[(t - 64) * 64 + ci];
    __syncthreads();
    if (t < 252) {
        int tap = t / 28, co = t % 28;
        float s = 0.f;
        if (co < 18) {
            for (int c = 0; c < 64; c++) s += w_off2[(co * 64 + c) * 9 + tap] * s1o[c];
        } else if (co < 27) {
            int cm = co - 18;
            for (int c = 0; c < 64; c++) s += w_mask2[(cm * 64 + c) * 9 + tap] * s1m[c];
        }
        g_wc[ci * 252 + tap * 28 + co] = s;
    }
}

// ---------------- kernel 1: fused 3x3 conv, split-K (32 ci per block) ----------------
// block 128 thr = 32 cols x 4 row-slots; px A = row ty, px B = row ty+4.
__global__ __launch_bounds__(128, 5) void k_conv3x3full(const float* __restrict__ x)
{
    __shared__ __align__(16) float tile[8][10][35];
    __shared__ __align__(16) float sw[2016];         // [ci 8][tap 9][co 28]
    int tid = threadIdx.x;
    int bz = blockIdx.z;
    int b = bz >> 1, half = bz & 1;
    int tx0 = blockIdx.x * 32, ty0 = blockIdx.y * 8;
    int tx = tid & 31, ty = tid >> 5;   // ty 0..3

    u64 accA[14], accB[14];
#pragma unroll
    for (int j = 0; j < 14; j++) { accA[j] = 0ULL; accB[j] = 0ULL; }

    for (int ch = 0; ch < 4; ch++) {
        int ci0 = half * 32 + ch * 8;
        __syncthreads();
        for (int i = tid; i < 8 * 10 * 34; i += 128) {
            int ci = i / 340, r = i % 340, iy = r / 34, ix = r % 34;
            int gy = ty0 - 1 + iy, gx = tx0 - 1 + ix;
            float v = 0.f;
            if ((unsigned)gy < 128u && (unsigned)gx < 128u)
                v = x[((size_t)(b * 64 + ci0 + ci)) * HWN + gy * WN + gx];
            tile[ci][iy][ix] = v;
        }
        for (int i = tid; i < 2016; i += 128)
            sw[i] = g_wc[ci0 * 252 + i];
        __syncthreads();

#pragma unroll 1
        for (int ci = 0; ci < 8; ci++) {
#pragma unroll
            for (int ky = 0; ky < 3; ky++) {
                const float* rowA = &tile[ci][ty + ky][tx];
                const float* rowB = &tile[ci][ty + 4 + ky][tx];
#pragma unroll
                for (int kx = 0; kx < 3; kx++) {
                    u64 xA = pack2(rowA[kx], rowA[kx]);
                    u64 xB = pack2(rowB[kx], rowB[kx]);
                    const u64* wp = (const u64*)&sw[ci * 252 + (ky * 3 + kx) * 28];
#pragma unroll
                    for (int j = 0; j < 14; j++) {
                        u64 w = wp[j];
                        accA[j] = fma2(xA, w, accA[j]);
                        accB[j] = fma2(xB, w, accB[j]);
                    }
                }
            }
        }
    }

    float* offp  = g_offp  + (size_t)half * (BN * 18 * HWN);
    float* maskp = g_maskp + (size_t)half * (BN * 9 * HWN);
#pragma unroll
    for (int px = 0; px < 2; px++) {
        int hw = (ty0 + ty + px * 4) * WN + tx0 + tx;
        const u64* acc = px ? accB : accA;
        float o[28];
#pragma unroll
        for (int j = 0; j < 14; j++) { float2 v = unpack2(acc[j]); o[2 * j] = v.x; o[2 * j + 1] = v.y; }
#pragma unroll
        for (int co = 0; co < 18; co++)
            offp[((size_t)(b * 18 + co)) * HWN + hw] = o[co];
#pragma unroll
        for (int k = 0; k < 9; k++)
            maskp[((size_t)(b * 9 + k)) * HWN + hw] = o[18 + k];
    }
}

// ---------------- kernel 2: deformable sampling, channel-last tile + f32x2 ----------------
__global__ __launch_bounds__(128, 5) void k_deform(const float* __restrict__ x,
                                                   const float* __restrict__ wq,
                                                   const float* __restrict__ bias,
                                                   float* __restrict__ out)
{
    __shared__ __align__(16) float tile[12 * 41 * TCH];  // [iy][ix][ci(20)]  39.4KB
    __shared__ float s_w[9 * 64];                        // [k][ci]
    int tid = threadIdx.x;
    int b = blockIdx.z;
    int tx0 = blockIdx.x * 32, ty0 = blockIdx.y * 4;
    int tx = tid & 31, ty = tid >> 5;
    int gh = ty0 + ty, gw = tx0 + tx;
    int hw = gh * WN + gw;

    for (int i = tid; i < 576; i += 128) s_w[i] = wq[(i & 63) * 9 + (i >> 6)];

    float a00[9], a01[9], a10[9], a11[9];
    int lyA[9], lxA[9];
    const float* o0 = g_offp + (size_t)b * 18 * HWN + hw;
    const float* o1 = o0 + (size_t)BN * 18 * HWN;
    const float* m0 = g_maskp + (size_t)b * 9 * HWN + hw;
    const float* m1 = m0 + (size_t)BN * 9 * HWN;
#pragma unroll
    for (int k = 0; k < 9; k++) {
        int ky = k / 3 - 1, kx = k % 3 - 1;
        float oy = o0[(size_t)(2 * k) * HWN] + o1[(size_t)(2 * k) * HWN];
        float ox = o0[(size_t)(2 * k + 1) * HWN] + o1[(size_t)(2 * k + 1) * HWN];
        float mraw = m0[(size_t)k * HWN] + m1[(size_t)k * HWN];
        float m = 1.f / (1.f + __expf(-mraw));
        float py = (float)(gh + ky) + oy;
        float px = (float)(gw + kx) + ox;
        float yf = floorf(py), xf = floorf(px);
        float wy = py - yf, wx = px - xf;
        float b1 = m * wy, b0v = m - b1;
        a00[k] = b0v - b0v * wx; a01[k] = b0v * wx;
        a10[k] = b1 - b1 * wx;  a11[k] = b1 * wx;
        lyA[k] = (int)yf - (ty0 - 4);
        lxA[k] = (int)xf - (tx0 - 4);
    }

    for (int ch = 0; ch < 4; ch++) {
        int ci0 = ch * 16;
        __syncthreads();
        for (int i = tid; i < 12 * 41 * 16; i += 128) {
            int ci = i / 492, r = i % 492, iy = r / 41, ix = r % 41;
            int gy = ty0 - 4 + iy, gx = tx0 - 4 + ix;
            float v = 0.f;
            if ((unsigned)gy < 128u && (unsigned)gx < 128u)
                v = x[((size_t)(b * 64 + ci0 + ci)) * HWN + gy * WN + gx];
            tile[(iy * 41 + ix) * TCH + ci] = v;
        }
        __syncthreads();

        u64 acc2[8];
#pragma unroll
        for (int j = 0; j < 8; j++) acc2[j] = 0ULL;

#pragma unroll
        for (int k = 0; k < 9; k++) {
            int ly = lyA[k], lx = lxA[k];
            if ((unsigned)ly < 11u && (unsigned)lx < 40u) {
                const float4* t4 = (const float4*)&tile[(ly * 41 + lx) * TCH];
                u64 C00 = pack2(a00[k], a00[k]);
                u64 C01 = pack2(a01[k], a01[k]);
                u64 C10 = pack2(a10[k], a10[k]);
                u64 C11 = pack2(a11[k], a11[k]);
                const u64* wk = (const u64*)&s_w[k * 64 + ci0];
#pragma unroll
                for (int cg = 0; cg < 4; cg++) {
                    float4 q00 = t4[cg];
                    float4 q01 = t4[5 + cg];          // lx+1  (+TCH floats)
                    float4 q10 = t4[205 + cg];        // ly+1  (+41*TCH floats)
                    float4 q11 = t4[210 + cg];
                    u64 tl = mul2(C00, pack2(q00.x, q00.y));
                    tl = fma2(C01, pack2(q01.x, q01.y), tl);
                    tl = fma2(C10, pack2(q10.x, q10.y), tl);
                    tl = fma2(C11, pack2(q11.x, q11.y), tl);
                    acc2[cg * 2] = fma2(wk[cg * 2], tl, acc2[cg * 2]);
                    u64 th = mul2(C00, pack2(q00.z, q00.w));
                    th = fma2(C01, pack2(q01.z, q01.w), th);
                    th = fma2(C10, pack2(q10.z, q10.w), th);
                    th = fma2(C11, pack2(q11.z, q11.w), th);
                    acc2[cg * 2 + 1] = fma2(wk[cg * 2 + 1], th, acc2[cg * 2 + 1]);
                }
            } else {
                int y0 = ly + ty0 - 4, x0v = lx + tx0 - 4;
                int y1 = y0 + 1, x1 = x0v + 1;
                bool v00 = (unsigned)y0 < 128u && (unsigned)x0v < 128u;
                bool v01 = (unsigned)y0 < 128u && (unsigned)x1 < 128u;
                bool v10 = (unsigned)y1 < 128u && (unsigned)x0v < 128u;
                bool v11 = (unsigned)y1 < 128u && (unsigned)x1 < 128u;
                float c00 = a00[k], c01 = a01[k], c10 = a10[k], c11 = a11[k];
                const float* xb = x + ((size_t)(b * 64 + ci0)) * HWN;
#pragma unroll
                for (int j = 0; j < 8; j++) {
                    const float* plo = xb + (size_t)(2 * j) * HWN;
                    const float* phi = plo + HWN;
                    float slo = c00 * (v00 ? __ldg(plo + y0 * WN + x0v) : 0.f)
                              + c01 * (v01 ? __ldg(plo + y0 * WN + x1) : 0.f)
                              + c10 * (v10 ? __ldg(plo + y1 * WN + x0v) : 0.f)
                              + c11 * (v11 ? __ldg(plo + y1 * WN + x1) : 0.f);
                    float shi = c00 * (v00 ? __ldg(phi + y0 * WN + x0v) : 0.f)
                              + c01 * (v01 ? __ldg(phi + y0 * WN + x1) : 0.f)
                              + c10 * (v10 ? __ldg(phi + y1 * WN + x0v) : 0.f)
                              + c11 * (v11 ? __ldg(phi + y1 * WN + x1) : 0.f);
                    float wlo = s_w[k * 64 + ci0 + 2 * j];
                    float whi = s_w[k * 64 + ci0 + 2 * j + 1];
                    acc2[j] = fma2(pack2(wlo, whi), pack2(slo, shi), acc2[j]);
                }
            }
        }
#pragma unroll
        for (int j = 0; j < 8; j++) {
            float2 v = unpack2(acc2[j]);
            int c = ci0 + 2 * j;
            out[((size_t)(b * 64 + c)) * HWN + hw]     = v.x + bias[c];
            out[((size_t)(b * 64 + c + 1)) * HWN + hw] = v.y + bias[c + 1];
        }
    }
}

// ---------------- kernel 3: partial mean/var (8 segments per group) ----------------
__global__ __launch_bounds__(256) void k_stats(const float* __restrict__ o)
{
    int id = blockIdx.x;          // bg*8 + q
    int q = id & 7, bg = id >> 3;
    int b = bg >> 5, g = bg & 31;
    const float4* p = (const float4*)(o + ((size_t)(b * 64 + g * 2)) * HWN) + q * 1024;
    int tid = threadIdx.x;
    float s = 0.f, sq = 0.f;
#pragma unroll
    for (int i = 0; i < 4; i++) {
        float4 v = p[tid + i * 256];
        s += v.x + v.y + v.z + v.w;
        sq += v.x * v.x + v.y * v.y + v.z * v.z + v.w * v.w;
    }
    __shared__ float ss[256], sqs[256];
    ss[tid] = s; sqs[tid] = sq;
    __syncthreads();
    for (int st = 128; st > 0; st >>= 1) {
        if (tid < st) { ss[tid] += ss[tid + st]; sqs[tid] += sqs[tid + st]; }
        __syncthreads();
    }
    if (tid == 0) {
        g_part[id * 2 + 0] = ss[0];
        g_part[id * 2 + 1] = sqs[0];
    }
}

// ---------------- kernel 4: finalize stats + normalize + affine + GELU ----------------
__global__ __launch_bounds__(256) void k_gn_gelu(float* __restrict__ o,
                                                 const float* __restrict__ gamma,
                                                 const float* __restrict__ beta)
{
    __shared__ float s_sc, s_sh;
    size_t i0 = (size_t)blockIdx.x * 1024;
    int c = (int)((i0 >> 14) & 63);
    int b = (int)(i0 >> 20);
    int g = c >> 1;
    if (threadIdx.x == 0) {
        int base = (b * 32 + g) * 8;
        float s = 0.f, sq = 0.f;
#pragma unroll
        for (int q = 0; q < 8; q++) {
            s  += g_part[(base + q) * 2 + 0];
            sq += g_part[(base + q) * 2 + 1];
        }
        float mean = s * (1.f / 32768.f);
        float var  = sq * (1.f / 32768.f) - mean * mean;
        float rstd = rsqrtf(var + 1e-5f);
        float sc = rstd * gamma[c];
        s_sc = sc;
        s_sh = beta[c] - mean * sc;
    }
    __syncthreads();
    float sc = s_sc, sh = s_sh;
    size_t i4 = i0 / 4 + threadIdx.x;
    float4 v = ((float4*)o)[i4];
    float t;
    t = v.x * sc + sh; v.x = 0.5f * t * (1.f + erff(t * 0.70710678118654752f));
    t = v.y * sc + sh; v.y = 0.5f * t * (1.f + erff(t * 0.70710678118654752f));
    t = v.z * sc + sh; v.z = 0.5f * t * (1.f + erff(t * 0.70710678118654752f));
    t = v.w * sc + sh; v.w = 0.5f * t * (1.f + erff(t * 0.70710678118654752f));
    ((float4*)o)[i4] = v;
}

// ---------------- launch ----------------
extern "C" void kernel_launch(void* const* d_in, const int* in_sizes, int n_in,
                              void* d_out, int out_size)
{
    const float* x       = (const float*)d_in[0];
    const float* w_off1  = (const float*)d_in[1];
    const float* w_off2  = (const float*)d_in[2];
    const float* w_mask1 = (const float*)d_in[3];
    const float* w_mask2 = (const float*)d_in[4];
    const float* weight  = (const float*)d_in[5];
    const float* bias    = (const float*)d_in[6];
    const float* gamma   = (const float*)d_in[7];
    const float* beta    = (const float*)d_in[8];
    float* out = (float*)d_out;

    k_compose<<<64, 256>>>(w_off1, w_off2, w_mask1, w_mask2);
    k_conv3x3full<<<dim3(WN / 32, HN / 8, BN * 2), 128>>>(x);
    k_deform<<<dim3(WN / 32, HN / 4, BN), 128>>>(x, weight, bias, out);
    k_stats<<<1024, 256>>>(out);
    k_gn_gelu<<<4096, 256>>>(out, gamma, beta);
}

// round 6
// speedup vs baseline: 1.8596x; 1.1455x over previous
#include <cuda_runtime.h>
#include <math.h>

#define BN 4
#define CN 64
#define HN 128
#define WN 128
#define HWN 16384
#define TCH 20   // channel-last tile stride (16 ci + 4 pad)

// ---------------- scratch ----------------
__device__ float g_offp[2 * BN * 18 * HWN];   // split-K partial conv outputs (offsets)
__device__ float g_maskp[2 * BN * 9 * HWN];   // split-K partial conv outputs (pre-sigmoid mask)
__device__ float g_wc[64 * 9 * 28];           // composed weights [ci][tap][co28]
__device__ float g_part[BN * 64 * 32 * 2];    // per (b, blk, group): sum, sumsq

typedef unsigned long long u64;

__device__ __forceinline__ u64 fma2(u64 a, u64 b, u64 c) {
    u64 d; asm("fma.rn.f32x2 %0, %1, %2, %3;" : "=l"(d) : "l"(a), "l"(b), "l"(c)); return d;
}
__device__ __forceinline__ u64 mul2(u64 a, u64 b) {
    u64 d; asm("mul.rn.f32x2 %0, %1, %2;" : "=l"(d) : "l"(a), "l"(b)); return d;
}
__device__ __forceinline__ u64 pack2(float x, float y) {
    u64 d; asm("mov.b64 %0, {%1, %2};" : "=l"(d) : "f"(x), "f"(y)); return d;
}
__device__ __forceinline__ float2 unpack2(u64 v) {
    float2 r; asm("mov.b64 {%0, %1}, %2;" : "=f"(r.x), "=f"(r.y) : "l"(v)); return r;
}

// ---------------- kernel 0: compose 1x1 into 3x3 weights ----------------
__global__ __launch_bounds__(256) void k_compose(const float* __restrict__ w_off1,
                                                 const float* __restrict__ w_off2,
                                                 const float* __restrict__ w_mask1,
                                                 const float* __restrict__ w_mask2)
{
    int ci = blockIdx.x;
    __shared__ float s1o[64], s1m[64];
    int t = threadIdx.x;
    if (t < 64) s1o[t] = w_off1[t * 64 + ci];
    else if (t < 128) s1m[t - 64] = w_mask1[(t - 64) * 64 + ci];
    __syncthreads();
    if (t < 252) {
        int tap = t / 28, co = t % 28;
        float s = 0.f;
        if (co < 18) {
            for (int c = 0; c < 64; c++) s += w_off2[(co * 64 + c) * 9 + tap] * s1o[c];
        } else if (co < 27) {
            int cm = co - 18;
            for (int c = 0; c < 64; c++) s += w_mask2[(cm * 64 + c) * 9 + tap] * s1m[c];
        }
        g_wc[ci * 252 + tap * 28 + co] = s;
    }
}

// ---------------- kernel 1: fused 3x3 conv, split-K, 4 px/thread, co-split ----------------
// block 256 = 32 cols x 4 row-slots x 2 co-halves; tile 8 rows x 64 cols.
// each thread: px rows r0, r0+4; cols tx, tx+32; 14 output channels (h*14..h*14+13).
__global__ __launch_bounds__(256, 2) void k_conv(const float* __restrict__ x)
{
    __shared__ __align__(16) float tile[8][10][67];  // 8 ci, 10 rows, 66 cols (+1 pad)
    __shared__ __align__(16) float sw[2016];         // [ci 8][tap 9][co 28]
    int tid = threadIdx.x;
    int bz = blockIdx.z;
    int b = bz >> 1, half = bz & 1;
    int tx0 = blockIdx.x * 64, ty0 = blockIdx.y * 8;
    int tx = tid & 31;
    int s = tid >> 5;          // 0..7
    int r0 = s & 3;            // row slot
    int h = s >> 2;            // co half

    u64 a00[7], a01[7], a10[7], a11[7];
#pragma unroll
    for (int j = 0; j < 7; j++) { a00[j] = 0ULL; a01[j] = 0ULL; a10[j] = 0ULL; a11[j] = 0ULL; }

    for (int ch = 0; ch < 4; ch++) {
        int ci0 = half * 32 + ch * 8;
        __syncthreads();
        for (int i = tid; i < 8 * 10 * 66; i += 256) {
            int ci = i / 660, r = i % 660, iy = r / 66, ix = r % 66;
            int gy = ty0 - 1 + iy, gx = tx0 - 1 + ix;
            float v = 0.f;
            if ((unsigned)gy < 128u && (unsigned)gx < 128u)
                v = x[((size_t)(b * 64 + ci0 + ci)) * HWN + gy * WN + gx];
            tile[ci][iy][ix] = v;
        }
        for (int i = tid; i < 2016; i += 256)
            sw[i] = g_wc[ci0 * 252 + i];
        __syncthreads();

#pragma unroll 1
        for (int ci = 0; ci < 8; ci++) {
#pragma unroll
            for (int ky = 0; ky < 3; ky++) {
                const float* rA = &tile[ci][r0 + ky][tx];
                const float* rB = &tile[ci][r0 + 4 + ky][tx];
#pragma unroll
                for (int kx = 0; kx < 3; kx++) {
                    float f00 = rA[kx],     f01 = rA[kx + 32];
                    float f10 = rB[kx],     f11 = rB[kx + 32];
                    u64 X00 = pack2(f00, f00), X01 = pack2(f01, f01);
                    u64 X10 = pack2(f10, f10), X11 = pack2(f11, f11);
                    const u64* wp = (const u64*)&sw[ci * 252 + (ky * 3 + kx) * 28 + h * 14];
#pragma unroll
                    for (int j = 0; j < 7; j++) {
                        u64 w = wp[j];
                        a00[j] = fma2(X00, w, a00[j]);
                        a01[j] = fma2(X01, w, a01[j]);
                        a10[j] = fma2(X10, w, a10[j]);
                        a11[j] = fma2(X11, w, a11[j]);
                    }
                }
            }
        }
    }

    float* offp  = g_offp  + (size_t)half * (BN * 18 * HWN) + (size_t)b * 18 * HWN;
    float* maskp = g_maskp + (size_t)half * (BN * 9 * HWN) + (size_t)b * 9 * HWN;
#pragma unroll
    for (int p = 0; p < 2; p++) {
#pragma unroll
        for (int qc = 0; qc < 2; qc++) {
            int hw = (ty0 + r0 + p * 4) * WN + tx0 + tx + qc * 32;
            const u64* acc = p ? (qc ? a11 : a10) : (qc ? a01 : a00);
#pragma unroll
            for (int j = 0; j < 7; j++) {
                float2 v = unpack2(acc[j]);
                int c0 = h * 14 + 2 * j;
#pragma unroll
                for (int e = 0; e < 2; e++) {
                    int co = c0 + e;
                    float val = e ? v.y : v.x;
                    if (co < 18) offp[(size_t)co * HWN + hw] = val;
                    else if (co < 27) maskp[(size_t)(co - 18) * HWN + hw] = val;
                }
            }
        }
    }
}

// ---------------- kernel 2: deformable sampling + GN partial stats ----------------
// block 256 = 8 rows x 32 cols; halo 4 -> tile 16x41, channel-last.
__global__ __launch_bounds__(256, 2) void k_deform(const float* __restrict__ x,
                                                   const float* __restrict__ wq,
                                                   const float* __restrict__ bias,
                                                   float* __restrict__ out)
{
    __shared__ __align__(16) float tile[16 * 41 * TCH];  // 52.5KB
    __shared__ float s_w[9 * 64];                        // [k][ci]
    __shared__ float red[8][16];
    int tid = threadIdx.x;
    int b = blockIdx.z;
    int tx0 = blockIdx.x * 32, ty0 = blockIdx.y * 8;
    int blk = blockIdx.y * 4 + blockIdx.x;               // 0..63
    int hy0 = ty0 - 4, hx0 = tx0 - 4;
    int tx = tid & 31, ty = tid >> 5;                    // ty 0..7
    int gh = ty0 + ty, gw = tx0 + tx;
    int hw = gh * WN + gw;
    int lane = tid & 31, wid = tid >> 5;

    for (int i = tid; i < 576; i += 256) s_w[i] = wq[(i & 63) * 9 + (i >> 6)];

    float a00[9], a01[9], a10[9], a11[9];
    int lyA[9], lxA[9];
    const float* o0 = g_offp + (size_t)b * 18 * HWN + hw;
    const float* o1 = o0 + (size_t)BN * 18 * HWN;
    const float* m0 = g_maskp + (size_t)b * 9 * HWN + hw;
    const float* m1 = m0 + (size_t)BN * 9 * HWN;
#pragma unroll
    for (int k = 0; k < 9; k++) {
        int ky = k / 3 - 1, kx = k % 3 - 1;
        float oy = o0[(size_t)(2 * k) * HWN] + o1[(size_t)(2 * k) * HWN];
        float ox = o0[(size_t)(2 * k + 1) * HWN] + o1[(size_t)(2 * k + 1) * HWN];
        float mraw = m0[(size_t)k * HWN] + m1[(size_t)k * HWN];
        float m = 1.f / (1.f + __expf(-mraw));
        float py = (float)(gh + ky) + oy;
        float px = (float)(gw + kx) + ox;
        float yf = floorf(py), xf = floorf(px);
        float wy = py - yf, wx = px - xf;
        float b1 = m * wy, b0v = m - b1;
        a00[k] = b0v - b0v * wx; a01[k] = b0v * wx;
        a10[k] = b1 - b1 * wx;  a11[k] = b1 * wx;
        lyA[k] = (int)yf - hy0;
        lxA[k] = (int)xf - hx0;
    }

    for (int ch = 0; ch < 4; ch++) {
        int ci0 = ch * 16;
        __syncthreads();
        for (int i = tid; i < 16 * 41 * 16; i += 256) {
            int ci = i / 656, r = i % 656, iy = r / 41, ix = r % 41;
            int gy = hy0 + iy, gx = hx0 + ix;
            float v = 0.f;
            if ((unsigned)gy < 128u && (unsigned)gx < 128u)
                v = x[((size_t)(b * 64 + ci0 + ci)) * HWN + gy * WN + gx];
            tile[(iy * 41 + ix) * TCH + ci] = v;
        }
        __syncthreads();

        u64 acc2[8];
#pragma unroll
        for (int j = 0; j < 8; j++) acc2[j] = 0ULL;

#pragma unroll
        for (int k = 0; k < 9; k++) {
            int ly = lyA[k], lx = lxA[k];
            if ((unsigned)ly < 15u && (unsigned)lx < 40u) {
                const float4* t4 = (const float4*)&tile[(ly * 41 + lx) * TCH];
                u64 C00 = pack2(a00[k], a00[k]);
                u64 C01 = pack2(a01[k], a01[k]);
                u64 C10 = pack2(a10[k], a10[k]);
                u64 C11 = pack2(a11[k], a11[k]);
                const u64* wk = (const u64*)&s_w[k * 64 + ci0];
#pragma unroll
                for (int cg = 0; cg < 4; cg++) {
                    float4 q00 = t4[cg];
                    float4 q01 = t4[5 + cg];          // lx+1
                    float4 q10 = t4[205 + cg];        // ly+1
                    float4 q11 = t4[210 + cg];
                    u64 tl = mul2(C00, pack2(q00.x, q00.y));
                    tl = fma2(C01, pack2(q01.x, q01.y), tl);
                    tl = fma2(C10, pack2(q10.x, q10.y), tl);
                    tl = fma2(C11, pack2(q11.x, q11.y), tl);
                    acc2[cg * 2] = fma2(wk[cg * 2], tl, acc2[cg * 2]);
                    u64 th = mul2(C00, pack2(q00.z, q00.w));
                    th = fma2(C01, pack2(q01.z, q01.w), th);
                    th = fma2(C10, pack2(q10.z, q10.w), th);
                    th = fma2(C11, pack2(q11.z, q11.w), th);
                    acc2[cg * 2 + 1] = fma2(wk[cg * 2 + 1], th, acc2[cg * 2 + 1]);
                }
            } else {
                int y0 = ly + hy0, x0v = lx + hx0;
                int y1 = y0 + 1, x1 = x0v + 1;
                bool v00 = (unsigned)y0 < 128u && (unsigned)x0v < 128u;
                bool v01 = (unsigned)y0 < 128u && (unsigned)x1 < 128u;
                bool v10 = (unsigned)y1 < 128u && (unsigned)x0v < 128u;
                bool v11 = (unsigned)y1 < 128u && (unsigned)x1 < 128u;
                float c00 = a00[k], c01 = a01[k], c10 = a10[k], c11 = a11[k];
                const float* xb = x + ((size_t)(b * 64 + ci0)) * HWN;
#pragma unroll
                for (int j = 0; j < 8; j++) {
                    const float* plo = xb + (size_t)(2 * j) * HWN;
                    const float* phi = plo + HWN;
                    float slo = c00 * (v00 ? __ldg(plo + y0 * WN + x0v) : 0.f)
                              + c01 * (v01 ? __ldg(plo + y0 * WN + x1) : 0.f)
                              + c10 * (v10 ? __ldg(plo + y1 * WN + x0v) : 0.f)
                              + c11 * (v11 ? __ldg(plo + y1 * WN + x1) : 0.f);
                    float shi = c00 * (v00 ? __ldg(phi + y0 * WN + x0v) : 0.f)
                              + c01 * (v01 ? __ldg(phi + y0 * WN + x1) : 0.f)
                              + c10 * (v10 ? __ldg(phi + y1 * WN + x0v) : 0.f)
                              + c11 * (v11 ? __ldg(phi + y1 * WN + x1) : 0.f);
                    float wlo = s_w[k * 64 + ci0 + 2 * j];
                    float whi = s_w[k * 64 + ci0 + 2 * j + 1];
                    acc2[j] = fma2(pack2(wlo, whi), pack2(slo, shi), acc2[j]);
                }
            }
        }

        // write out + per-group (sum, sumsq) partials
        float sv[8], qv[8];
#pragma unroll
        for (int j = 0; j < 8; j++) {
            float2 v = unpack2(acc2[j]);
            int c = ci0 + 2 * j;
            float vx = v.x + __ldg(bias + c);
            float vy = v.y + __ldg(bias + c + 1);
            out[((size_t)(b * 64 + c)) * HWN + hw]     = vx;
            out[((size_t)(b * 64 + c + 1)) * HWN + hw] = vy;
            sv[j] = vx + vy;
            qv[j] = vx * vx + vy * vy;
        }
#pragma unroll
        for (int off = 16; off > 0; off >>= 1) {
#pragma unroll
            for (int j = 0; j < 8; j++) {
                sv[j] += __shfl_down_sync(0xffffffffu, sv[j], off);
                qv[j] += __shfl_down_sync(0xffffffffu, qv[j], off);
            }
        }
        if (lane == 0) {
#pragma unroll
            for (int j = 0; j < 8; j++) { red[wid][j] = sv[j]; red[wid][8 + j] = qv[j]; }
        }
        __syncthreads();
        if (tid < 16) {
            float tot = 0.f;
#pragma unroll
            for (int w = 0; w < 8; w++) tot += red[w][tid];
            int g = (ci0 >> 1) + (tid & 7);
            g_part[((b * 64 + blk) * 32 + g) * 2 + (tid >> 3)] = tot;
        }
    }
}

// ---------------- kernel 3: finalize stats + normalize + affine + GELU ----------------
__global__ __launch_bounds__(256) void k_gn_gelu(float* __restrict__ o,
                                                 const float* __restrict__ gamma,
                                                 const float* __restrict__ beta)
{
    __shared__ float sp[64], sq2[64];
    __shared__ float s_sc, s_sh;
    size_t i0 = (size_t)blockIdx.x * 1024;
    int c = (int)((i0 >> 14) & 63);
    int b = (int)(i0 >> 20);
    int g = c >> 1;
    int t = threadIdx.x;
    if (t < 64) {
        sp[t]  = g_part[((b * 64 + t) * 32 + g) * 2 + 0];
        sq2[t] = g_part[((b * 64 + t) * 32 + g) * 2 + 1];
    }
    __syncthreads();
    if (t == 0) {
        float s = 0.f, sq = 0.f;
#pragma unroll
        for (int i = 0; i < 64; i++) { s += sp[i]; sq += sq2[i]; }
        float mean = s * (1.f / 32768.f);
        float var  = sq * (1.f / 32768.f) - mean * mean;
        float rstd = rsqrtf(var + 1e-5f);
        float sc = rstd * gamma[c];
        s_sc = sc;
        s_sh = beta[c] - mean * sc;
    }
    __syncthreads();
    float sc = s_sc, sh = s_sh;
    size_t i4 = i0 / 4 + t;
    float4 v = ((float4*)o)[i4];
    float tt;
    tt = v.x * sc + sh; v.x = 0.5f * tt * (1.f + erff(tt * 0.70710678118654752f));
    tt = v.y * sc + sh; v.y = 0.5f * tt * (1.f + erff(tt * 0.70710678118654752f));
    tt = v.z * sc + sh; v.z = 0.5f * tt * (1.f + erff(tt * 0.70710678118654752f));
    tt = v.w * sc + sh; v.w = 0.5f * tt * (1.f + erff(tt * 0.70710678118654752f));
    ((float4*)o)[i4] = v;
}

// ---------------- launch ----------------
extern "C" void kernel_launch(void* const* d_in, const int* in_sizes, int n_in,
                              void* d_out, int out_size)
{
    const float* x       = (const float*)d_in[0];
    const float* w_off1  = (const float*)d_in[1];
    const float* w_off2  = (const float*)d_in[2];
    const float* w_mask1 = (const float*)d_in[3];
    const float* w_mask2 = (const float*)d_in[4];
    const float* weight  = (const float*)d_in[5];
    const float* bias    = (const float*)d_in[6];
    const float* gamma   = (const float*)d_in[7];
    const float* beta    = (const float*)d_in[8];
    float* out = (float*)d_out;

    k_compose<<<64, 256>>>(w_off1, w_off2, w_mask1, w_mask2);
    k_conv<<<dim3(2, 16, BN * 2), 256>>>(x);
    k_deform<<<dim3(4, 16, BN), 256>>>(x, weight, bias, out);
    k_gn_gelu<<<4096, 256>>>(out, gamma, beta);
}